// round 14
// baseline (speedup 1.0000x reference)
#include <cuda_runtime.h>
#include <cuda_bf16.h>
#include <cstdint>
#include <algorithm>

// ---------------------------------------------------------------------------
// UniformNeighborSampler:
//   out[r, j] = (float) adj[g_id, ids[r], sel[j]],  g_id=1, ins=1 (adj_ins)
//   sel = jax.random.permutation(jax.random.key(42), 128)[:32]
//     (partitionable threefry, verified exact since R4)
//
// R14: L1tex sector-rate theory. All prior shapes make L1 chew ~14 distinct
// 32B sectors per row (~2cyc each => ~46cyc/row/SM => 8.6us). Fix: load each
// 512B row with ONE coalesced LDG.128 warp-instruction (4 clean 128B
// wavefronts), then pick the 32 sampled columns entirely in registers via
// 4 SHFLs (one per int4 component; target lane pulls from lane sel>>2) +
// selects. No smem, no banks. 8 rows/warp front-batched.
// ---------------------------------------------------------------------------

namespace {

constexpr int N_GRAPHS      = 4;
constexpr int DEGREES       = 128;
constexpr int SAMPLES       = 32;
constexpr int G_ID          = 1;
constexpr int ROWS_PER_WARP = 8;
constexpr int WARPS_PER_BLK = 8;

struct Sel32 { int s[SAMPLES]; };

static inline uint32_t rotl32(uint32_t x, int d) {
    return (x << d) | (x >> (32 - d));
}

static void threefry2x32(uint32_t k0, uint32_t k1,
                         uint32_t c0, uint32_t c1,
                         uint32_t* o0, uint32_t* o1) {
    uint32_t ks[3] = {k0, k1, k0 ^ k1 ^ 0x1BD11BDAu};
    uint32_t x0 = c0 + ks[0];
    uint32_t x1 = c1 + ks[1];
    static const int rot[2][4] = {{13, 15, 26, 6}, {17, 29, 16, 24}};
    for (int i = 0; i < 5; i++) {
        const int* r = rot[i & 1];
        for (int j = 0; j < 4; j++) {
            x0 += x1;
            x1 = rotl32(x1, r[j]);
            x1 ^= x0;
        }
        x0 += ks[(i + 1) % 3];
        x1 += ks[(i + 2) % 3] + (uint32_t)(i + 1);
    }
    *o0 = x0;
    *o1 = x1;
}

static void compute_sel(Sel32* sel) {
    const uint32_t k0 = 0u, k1 = 42u;          // jax.random.key(42)

    uint32_t sk0, sk1;                          // partitionable split
    threefry2x32(k0, k1, 0u, 1u, &sk0, &sk1);

    uint32_t bits[DEGREES];                     // counter-mode bits, xor-fold
    for (int i = 0; i < DEGREES; i++) {
        uint32_t y0, y1;
        threefry2x32(sk0, sk1, 0u, (uint32_t)i, &y0, &y1);
        bits[i] = y0 ^ y1;
    }

    uint64_t kv[DEGREES];
    for (int i = 0; i < DEGREES; i++)
        kv[i] = ((uint64_t)bits[i] << 32) | (uint32_t)i;
    std::sort(kv, kv + DEGREES);

    for (int j = 0; j < SAMPLES; j++)
        sel->s[j] = (int)(kv[j] & 0xFFFFFFFFu);
}

} // namespace

__global__ __launch_bounds__(WARPS_PER_BLK * 32)
void uniform_neighbor_sampler_kernel(const int* __restrict__ adj_g,
                                     const int* __restrict__ ids,
                                     float* __restrict__ out,
                                     int batch, Sel32 sel)
{
    const int lane = threadIdx.x & 31;
    const int warp = (int)((blockIdx.x * blockDim.x + threadIdx.x) >> 5);

    const long long row0 = (long long)warp * ROWS_PER_WARP;
    if (row0 >= batch) return;

    // Coalesced ids load: lanes 0..7 fetch the 8 row ids.
    int myid = 0;
    if (lane < ROWS_PER_WARP && row0 + lane < batch)
        myid = __ldg(&ids[row0 + lane]);

    const int col     = sel.s[lane];
    const int srclane = col >> 2;      // lane holding col's int4 chunk
    const int sub     = col & 3;       // component within that int4

    // Full-row coalesced loads: one LDG.128 warp-instr per row
    // (32 lanes x 16B = 512B = 4 clean 128B wavefronts). Front-batched MLP=8.
    int4 v[ROWS_PER_WARP];
#pragma unroll
    for (int r = 0; r < ROWS_PER_WARP; r++) {
        int id = __shfl_sync(0xffffffffu, myid, r);
        v[r] = __ldg(reinterpret_cast<const int4*>(
                         adj_g + (long long)id * DEGREES) + lane);
    }

    // Register pick: 4 SHFLs route all 4 candidate components from srclane,
    // 2-level select keeps the sampled one. Coalesced 128B store per row.
#pragma unroll
    for (int r = 0; r < ROWS_PER_WARP; r++) {
        int a = __shfl_sync(0xffffffffu, v[r].x, srclane);
        int b = __shfl_sync(0xffffffffu, v[r].y, srclane);
        int c = __shfl_sync(0xffffffffu, v[r].z, srclane);
        int d = __shfl_sync(0xffffffffu, v[r].w, srclane);
        int x = (sub < 2) ? ((sub == 0) ? a : b)
                          : ((sub == 2) ? c : d);
        long long row = row0 + r;
        if (row < batch)
            out[row * SAMPLES + lane] = (float)x;
    }
}

extern "C" void kernel_launch(void* const* d_in, const int* in_sizes, int n_in,
                              void* d_out, int out_size)
{
    // Locate inputs by SIZE (layout-order independent).
    int adj_idx0 = -1, adj_idx1 = -1, ids_idx = -1;
    for (int i = 0; i < n_in; i++) {
        long long sz = in_sizes[i];
        if (sz > 1000000) {
            if (adj_idx0 < 0) adj_idx0 = i;
            else if (adj_idx1 < 0) adj_idx1 = i;
        } else if (sz > 1) {
            ids_idx = i;
        }
    }
    if (adj_idx0 < 0) adj_idx0 = 0;
    if (adj_idx1 < 0) adj_idx1 = 1;
    if (ids_idx  < 0) ids_idx  = 3;

    const int* adj_ins = (const int*)d_in[adj_idx0];   // ins=1 -> active table
    const int* ids     = (const int*)d_in[ids_idx];

    const int num_nodes = in_sizes[adj_idx0] / (N_GRAPHS * DEGREES);
    const int batch     = in_sizes[ids_idx];           // 50000 rows

    const int* adj_g = adj_ins + (long long)G_ID * num_nodes * DEGREES;

    Sel32 sel;
    compute_sel(&sel);

    const int threads = WARPS_PER_BLK * 32;            // 256
    const int rows_per_block = WARPS_PER_BLK * ROWS_PER_WARP;  // 64
    const int blocks = (batch + rows_per_block - 1) / rows_per_block;  // 782

    uniform_neighbor_sampler_kernel<<<blocks, threads>>>(
        adj_g, ids, (float*)d_out, batch, sel);
}